// round 1
// baseline (speedup 1.0000x reference)
#include <cuda_runtime.h>

// Tiny fused transformer: B=16384, T=64, D=3, HD=4, FF=2, VOCAB=10.
// One token per thread, BPB batches per 256-thread block.
// k/v tiles live in shared memory (broadcast LDS.128 in the attention loop).
// Softmax runs max-free (scores bounded: |score| <= 0.5*|q||k| <~ 4 after
// RMS norm x w_qn), exp folded to a single ex2.approx via 0.5*log2e in q.

#define T 64
#define BPB 4
#define NTHREADS (BPB * T)
#define VOCAB 10

__device__ __forceinline__ float ex2f(float x) {
    float y;
    asm("ex2.approx.ftz.f32 %0, %1;" : "=f"(y) : "f"(x));
    return y;
}
__device__ __forceinline__ float rcpf(float x) {
    float y;
    asm("rcp.approx.ftz.f32 %0, %1;" : "=f"(y) : "f"(x));
    return y;
}

__global__ __launch_bounds__(NTHREADS)
void adder_model_kernel(
    const int* __restrict__ idx,
    const float* __restrict__ pA,
    const float* __restrict__ pStart,
    const float* __restrict__ pStride,
    const float* __restrict__ w_ln1,
    const float* __restrict__ w_ln2,
    const float* __restrict__ w_lnf,
    const float* __restrict__ w_qn,
    const float* __restrict__ Wq,
    const float* __restrict__ Wk,
    const float* __restrict__ Wg,
    const float* __restrict__ Wu,
    const float* __restrict__ Wd,
    float* __restrict__ out)
{
    __shared__ float2 table_sh[VOCAB];
    __shared__ float4 k_sh[BPB][T];
    __shared__ float4 v_sh[BPB][T];
    __shared__ float  logits_sh[BPB * T * VOCAB];

    const int tid   = threadIdx.x;
    const int local = tid >> 6;          // batch within block
    const int t     = tid & 63;          // token
    const int b     = blockIdx.x * BPB + local;

    const float A       = pA[0];
    const float astart  = pStart[0];
    const float astride = pStride[0];

    // digit table (shared across block)
    if (tid < VOCAB) {
        float s, c;
        sincosf(astart + (float)tid * astride, &s, &c);
        table_sh[tid] = make_float2(A * c, A * s);
    }

    // ---- embedding ----
    const int dig = idx[b * T + t];
    float sa, ca;
    sincosf(astart + (float)dig * astride, &sa, &ca);
    float x0 = A * ca;
    float x1 = A * sa;
    float x2 = sinf((float)t * 1.0e-4f);   // pe = sin(t * exp(-ln 1e4))

    // ---- RMS ln1 ----
    float ms = (x0 * x0 + x1 * x1 + x2 * x2) * (1.0f / 3.0f) + 1e-6f;
    float r  = rsqrtf(ms);
    float h0 = x0 * r * w_ln1[0];
    float h1 = x1 * r * w_ln1[1];
    float h2 = x2 * r * w_ln1[2];

    // ---- q/k/v projections (v shares the Wk product) ----
    float qr[4], kv[4];
#pragma unroll
    for (int j = 0; j < 4; ++j) {
        qr[j] = h0 * Wq[j * 3 + 0] + h1 * Wq[j * 3 + 1] + h2 * Wq[j * 3 + 2];
        kv[j] = h0 * Wk[j * 3 + 0] + h1 * Wk[j * 3 + 1] + h2 * Wk[j * 3 + 2];
    }

    const float wq0 = w_qn[0], wq1 = w_qn[1], wq2 = w_qn[2], wq3 = w_qn[3];
    float msq = (qr[0]*qr[0] + qr[1]*qr[1] + qr[2]*qr[2] + qr[3]*qr[3]) * 0.25f + 1e-6f;
    float rq  = rsqrtf(msq);
    float q0 = qr[0] * rq * wq0, q1 = qr[1] * rq * wq1;
    float q2 = qr[2] * rq * wq2, q3 = qr[3] * rq * wq3;

    float msk = (kv[0]*kv[0] + kv[1]*kv[1] + kv[2]*kv[2] + kv[3]*kv[3]) * 0.25f + 1e-6f;
    float rk  = rsqrtf(msk);
    float k0 = kv[0] * rk * wq0, k1 = kv[1] * rk * wq1;
    float k2 = kv[2] * rk * wq2, k3 = kv[3] * rk * wq3;

    // ---- RoPE (theta=3, HD=4 -> inv_freq = {1, 3^-0.5}) ----
    float s0, c0, s1, c1;
    sincosf((float)t, &s0, &c0);
    sincosf((float)t * 0.57735026918962576f, &s1, &c1);

    float Q0 = q0 * c0 - q1 * s0, Q1 = q0 * s0 + q1 * c0;
    float Q2 = q2 * c1 - q3 * s1, Q3 = q2 * s1 + q3 * c1;
    float K0 = k0 * c0 - k1 * s0, K1 = k0 * s0 + k1 * c0;
    float K2 = k2 * c1 - k3 * s1, K3 = k2 * s1 + k3 * c1;

    // fold softmax scale (HD^-0.5 = 0.5) and log2(e) into q
    const float SC = 0.5f * 1.4426950408889634f;
    Q0 *= SC; Q1 *= SC; Q2 *= SC; Q3 *= SC;

    k_sh[local][t] = make_float4(K0, K1, K2, K3);
    v_sh[local][t] = make_float4(kv[0], kv[1], kv[2], kv[3]);
    __syncthreads();

    // ---- causal attention, max-free single pass ----
    float sum = 0.0f, a0 = 0.0f, a1 = 0.0f, a2 = 0.0f, a3 = 0.0f;
#pragma unroll 4
    for (int s = 0; s <= t; ++s) {
        const float4 kk = k_sh[local][s];
        const float sc = Q0 * kk.x + Q1 * kk.y + Q2 * kk.z + Q3 * kk.w;
        const float p  = ex2f(sc);          // == exp(0.5 * q.k)
        sum += p;
        const float4 vv = v_sh[local][s];
        a0 += p * vv.x; a1 += p * vv.y; a2 += p * vv.z; a3 += p * vv.w;
    }
    const float inv = rcpf(sum);
    const float o0 = a0 * inv, o1 = a1 * inv, o2 = a2 * inv, o3 = a3 * inv;

    // ---- residual: x += out @ Wq  (Wq used untransposed here) ----
    x0 += o0 * Wq[0] + o1 * Wq[3] + o2 * Wq[6] + o3 * Wq[9];
    x1 += o0 * Wq[1] + o1 * Wq[4] + o2 * Wq[7] + o3 * Wq[10];
    x2 += o0 * Wq[2] + o1 * Wq[5] + o2 * Wq[8] + o3 * Wq[11];

    // ---- RMS ln2 + SwiGLU FFN ----
    ms = (x0 * x0 + x1 * x1 + x2 * x2) * (1.0f / 3.0f) + 1e-6f;
    r  = rsqrtf(ms);
    h0 = x0 * r * w_ln2[0];
    h1 = x1 * r * w_ln2[1];
    h2 = x2 * r * w_ln2[2];

    const float g0 = h0 * Wg[0] + h1 * Wg[1] + h2 * Wg[2];
    const float g1 = h0 * Wg[3] + h1 * Wg[4] + h2 * Wg[5];
    const float u0 = h0 * Wu[0] + h1 * Wu[1] + h2 * Wu[2];
    const float u1 = h0 * Wu[3] + h1 * Wu[4] + h2 * Wu[5];

    const float LOG2E = 1.4426950408889634f;
    const float m0 = g0 * u0 * rcpf(1.0f + ex2f(-g0 * LOG2E));  // silu(g0)*u0
    const float m1 = g1 * u1 * rcpf(1.0f + ex2f(-g1 * LOG2E));

    x0 += m0 * Wd[0] + m1 * Wd[1];
    x1 += m0 * Wd[2] + m1 * Wd[3];
    x2 += m0 * Wd[4] + m1 * Wd[5];

    // ---- final RMS (only first two channels feed the logits) ----
    ms = (x0 * x0 + x1 * x1 + x2 * x2) * (1.0f / 3.0f) + 1e-6f;
    r  = rsqrtf(ms);
    const float f0 = x0 * r * w_lnf[0];
    const float f1 = x1 * r * w_lnf[1];

    // ---- logits -> smem staging ----
    float* lg = &logits_sh[(local * T + t) * VOCAB];
#pragma unroll
    for (int vv = 0; vv < VOCAB; ++vv) {
        const float2 tb = table_sh[vv];
        lg[vv] = f0 * tb.x + f1 * tb.y;
    }
    __syncthreads();

    // ---- coalesced store: block owns a contiguous 2560-float span ----
    float2* dst2 = (float2*)(out + (size_t)blockIdx.x * (BPB * T * VOCAB));
    const float2* src2 = (const float2*)logits_sh;
#pragma unroll
    for (int i = tid; i < BPB * T * VOCAB / 2; i += NTHREADS)
        dst2[i] = src2[i];
}

extern "C" void kernel_launch(void* const* d_in, const int* in_sizes, int n_in,
                              void* d_out, int out_size)
{
    const int*   idx     = (const int*)  d_in[0];
    const float* arc_A   = (const float*)d_in[1];
    const float* arc_st  = (const float*)d_in[2];
    const float* arc_sd  = (const float*)d_in[3];
    const float* w_ln1   = (const float*)d_in[4];
    const float* w_ln2   = (const float*)d_in[5];
    const float* w_lnf   = (const float*)d_in[6];
    const float* w_qn    = (const float*)d_in[7];
    const float* Wq      = (const float*)d_in[8];
    const float* Wk      = (const float*)d_in[9];
    const float* Wg      = (const float*)d_in[10];
    const float* Wu      = (const float*)d_in[11];
    const float* Wd      = (const float*)d_in[12];
    float* out = (float*)d_out;

    const int B = in_sizes[0] / T;           // 16384
    const int grid = B / BPB;                // 4096 blocks
    adder_model_kernel<<<grid, NTHREADS>>>(idx, arc_A, arc_st, arc_sd,
                                           w_ln1, w_ln2, w_lnf, w_qn,
                                           Wq, Wk, Wg, Wu, Wd, out);
}

// round 2
// speedup vs baseline: 1.0344x; 1.0344x over previous
#include <cuda_runtime.h>

// Tiny fused transformer: B=16384, T=64, D=3, HD=4, FF=2, VOCAB=10.
// R2: attention inner loop vectorized 2 s-positions/iter with packed
// fma.rn.f32x2 (FFMA2, PTX-only on sm_103a). k/v in pair-interleaved smem so
// one LDS.128 feeds two packed operands. Max-free softmax (scores bounded),
// exp = single ex2.approx via 0.5*log2e folded into q.

#define T 64
#define BPB 4
#define NTHREADS (BPB * T)
#define VOCAB 10

typedef unsigned long long u64;

__device__ __forceinline__ float ex2f(float x) {
    float y; asm("ex2.approx.ftz.f32 %0, %1;" : "=f"(y) : "f"(x)); return y;
}
__device__ __forceinline__ float rcpf(float x) {
    float y; asm("rcp.approx.ftz.f32 %0, %1;" : "=f"(y) : "f"(x)); return y;
}
__device__ __forceinline__ u64 pack2(float lo, float hi) {
    u64 r; asm("mov.b64 %0, {%1, %2};" : "=l"(r) : "f"(lo), "f"(hi)); return r;
}
__device__ __forceinline__ void unpack2(u64 v, float& lo, float& hi) {
    asm("mov.b64 {%0, %1}, %2;" : "=f"(lo), "=f"(hi) : "l"(v));
}
__device__ __forceinline__ u64 fma2(u64 a, u64 b, u64 c) {
    u64 d; asm("fma.rn.f32x2 %0, %1, %2, %3;" : "=l"(d) : "l"(a), "l"(b), "l"(c)); return d;
}
__device__ __forceinline__ u64 mul2(u64 a, u64 b) {
    u64 d; asm("mul.rn.f32x2 %0, %1, %2;" : "=l"(d) : "l"(a), "l"(b)); return d;
}
__device__ __forceinline__ u64 add2(u64 a, u64 b) {
    u64 d; asm("add.rn.f32x2 %0, %1, %2;" : "=l"(d) : "l"(a), "l"(b)); return d;
}

__global__ __launch_bounds__(NTHREADS)
void adder_model_kernel(
    const int* __restrict__ idx,
    const float* __restrict__ pA,
    const float* __restrict__ pStart,
    const float* __restrict__ pStride,
    const float* __restrict__ w_ln1,
    const float* __restrict__ w_ln2,
    const float* __restrict__ w_lnf,
    const float* __restrict__ w_qn,
    const float* __restrict__ Wq,
    const float* __restrict__ Wk,
    const float* __restrict__ Wg,
    const float* __restrict__ Wu,
    const float* __restrict__ Wd,
    float* __restrict__ out)
{
    // pair-interleaved: kA[b][i] = {pack(k0[2i],k0[2i+1]), pack(k1[2i],k1[2i+1])}
    __shared__ ulonglong2 kA[BPB][T / 2];
    __shared__ ulonglong2 kB[BPB][T / 2];
    __shared__ ulonglong2 vA[BPB][T / 2];
    __shared__ ulonglong2 vB[BPB][T / 2];
    __shared__ float2 table_sh[VOCAB];
    __shared__ float  logits_sh[BPB * T * VOCAB];

    const int tid   = threadIdx.x;
    const int local = tid >> 6;          // batch within block
    const int t     = tid & 63;          // token
    const int b     = blockIdx.x * BPB + local;

    const float A       = pA[0];
    const float astart  = pStart[0];
    const float astride = pStride[0];

    if (tid < VOCAB) {
        float s, c;
        sincosf(astart + (float)tid * astride, &s, &c);
        table_sh[tid] = make_float2(A * c, A * s);
    }

    // ---- embedding ----
    const int dig = idx[b * T + t];
    float sa, ca;
    sincosf(astart + (float)dig * astride, &sa, &ca);
    float x0 = A * ca;
    float x1 = A * sa;
    float x2 = sinf((float)t * 1.0e-4f);   // pe = sin(t * exp(-ln 1e4))

    // ---- RMS ln1 ----
    float ms = (x0 * x0 + x1 * x1 + x2 * x2) * (1.0f / 3.0f) + 1e-6f;
    float r  = rsqrtf(ms);
    float h0 = x0 * r * w_ln1[0];
    float h1 = x1 * r * w_ln1[1];
    float h2 = x2 * r * w_ln1[2];

    // ---- q/k/v projections (v shares the Wk product) ----
    float qr[4], kv[4];
#pragma unroll
    for (int j = 0; j < 4; ++j) {
        qr[j] = h0 * Wq[j * 3 + 0] + h1 * Wq[j * 3 + 1] + h2 * Wq[j * 3 + 2];
        kv[j] = h0 * Wk[j * 3 + 0] + h1 * Wk[j * 3 + 1] + h2 * Wk[j * 3 + 2];
    }

    const float wq0 = w_qn[0], wq1 = w_qn[1], wq2 = w_qn[2], wq3 = w_qn[3];
    float msq = (qr[0]*qr[0] + qr[1]*qr[1] + qr[2]*qr[2] + qr[3]*qr[3]) * 0.25f + 1e-6f;
    float rq  = rsqrtf(msq);
    float q0 = qr[0] * rq * wq0, q1 = qr[1] * rq * wq1;
    float q2 = qr[2] * rq * wq2, q3 = qr[3] * rq * wq3;

    float msk = (kv[0]*kv[0] + kv[1]*kv[1] + kv[2]*kv[2] + kv[3]*kv[3]) * 0.25f + 1e-6f;
    float rk  = rsqrtf(msk);
    float k0 = kv[0] * rk * wq0, k1 = kv[1] * rk * wq1;
    float k2 = kv[2] * rk * wq2, k3 = kv[3] * rk * wq3;

    // ---- RoPE (theta=3, HD=4 -> inv_freq = {1, 3^-0.5}) ----
    float s0, c0, s1, c1;
    sincosf((float)t, &s0, &c0);
    sincosf((float)t * 0.57735026918962576f, &s1, &c1);

    float Q0 = q0 * c0 - q1 * s0, Q1 = q0 * s0 + q1 * c0;
    float Q2 = q2 * c1 - q3 * s1, Q3 = q2 * s1 + q3 * c1;
    float K0 = k0 * c0 - k1 * s0, K1 = k0 * s0 + k1 * c0;
    float K2 = k2 * c1 - k3 * s1, K3 = k2 * s1 + k3 * c1;

    // fold softmax scale (HD^-0.5 = 0.5) and log2(e) into q
    const float SC = 0.5f * 1.4426950408889634f;
    Q0 *= SC; Q1 *= SC; Q2 *= SC; Q3 *= SC;

    // ---- stage k/v into pair-interleaved smem ----
    {
        const int i = t >> 1, lane = t & 1;
        float* a = (float*)&kA[local][i]; a[lane] = K0; a[2 + lane] = K1;
        float* bb = (float*)&kB[local][i]; bb[lane] = K2; bb[2 + lane] = K3;
        float* c = (float*)&vA[local][i]; c[lane] = kv[0]; c[2 + lane] = kv[1];
        float* d = (float*)&vB[local][i]; d[lane] = kv[2]; d[2 + lane] = kv[3];
    }
    __syncthreads();

    // ---- causal attention, packed 2-wide, max-free single pass ----
    const u64 Q0d = pack2(Q0, Q0), Q1d = pack2(Q1, Q1);
    const u64 Q2d = pack2(Q2, Q2), Q3d = pack2(Q3, Q3);

    u64 sum2 = 0ULL, c0a = 0ULL, c1a = 0ULL, c2a = 0ULL, c3a = 0ULL;
    const int np = (t + 1) >> 1;      // full pairs: s in [0, 2*np)
#pragma unroll 4
    for (int i = 0; i < np; ++i) {
        const ulonglong2 ka = kA[local][i];
        const ulonglong2 kb = kB[local][i];
        const u64 sc2 = fma2(Q0d, ka.x, fma2(Q1d, ka.y, fma2(Q2d, kb.x, mul2(Q3d, kb.y))));
        float sl, sh; unpack2(sc2, sl, sh);
        const u64 p2 = pack2(ex2f(sl), ex2f(sh));
        sum2 = add2(sum2, p2);
        const ulonglong2 va = vA[local][i];
        const ulonglong2 vb = vB[local][i];
        c0a = fma2(p2, va.x, c0a);
        c1a = fma2(p2, va.y, c1a);
        c2a = fma2(p2, vb.x, c2a);
        c3a = fma2(p2, vb.y, c3a);
    }
    float sl, sh, a0, a1, a2, a3, tl, th;
    unpack2(sum2, sl, sh); float sum = sl + sh;
    unpack2(c0a, tl, th); a0 = tl + th;
    unpack2(c1a, tl, th); a1 = tl + th;
    unpack2(c2a, tl, th); a2 = tl + th;
    unpack2(c3a, tl, th); a3 = tl + th;

    if (!(t & 1)) {                   // leftover s = t (self-attention term)
        const float sc = Q0 * K0 + Q1 * K1 + Q2 * K2 + Q3 * K3;
        const float p  = ex2f(sc);
        sum += p;
        a0 += p * kv[0]; a1 += p * kv[1]; a2 += p * kv[2]; a3 += p * kv[3];
    }

    const float inv = rcpf(sum);
    const float o0 = a0 * inv, o1 = a1 * inv, o2 = a2 * inv, o3 = a3 * inv;

    // ---- residual: x += out @ Wq ----
    x0 += o0 * Wq[0] + o1 * Wq[3] + o2 * Wq[6] + o3 * Wq[9];
    x1 += o0 * Wq[1] + o1 * Wq[4] + o2 * Wq[7] + o3 * Wq[10];
    x2 += o0 * Wq[2] + o1 * Wq[5] + o2 * Wq[8] + o3 * Wq[11];

    // ---- RMS ln2 + SwiGLU FFN ----
    ms = (x0 * x0 + x1 * x1 + x2 * x2) * (1.0f / 3.0f) + 1e-6f;
    r  = rsqrtf(ms);
    h0 = x0 * r * w_ln2[0];
    h1 = x1 * r * w_ln2[1];
    h2 = x2 * r * w_ln2[2];

    const float g0 = h0 * Wg[0] + h1 * Wg[1] + h2 * Wg[2];
    const float g1 = h0 * Wg[3] + h1 * Wg[4] + h2 * Wg[5];
    const float u0 = h0 * Wu[0] + h1 * Wu[1] + h2 * Wu[2];
    const float u1 = h0 * Wu[3] + h1 * Wu[4] + h2 * Wu[5];

    const float LOG2E = 1.4426950408889634f;
    const float m0 = g0 * u0 * rcpf(1.0f + ex2f(-g0 * LOG2E));  // silu(g0)*u0
    const float m1 = g1 * u1 * rcpf(1.0f + ex2f(-g1 * LOG2E));

    x0 += m0 * Wd[0] + m1 * Wd[1];
    x1 += m0 * Wd[2] + m1 * Wd[3];
    x2 += m0 * Wd[4] + m1 * Wd[5];

    // ---- final RMS (only first two channels feed the logits) ----
    ms = (x0 * x0 + x1 * x1 + x2 * x2) * (1.0f / 3.0f) + 1e-6f;
    r  = rsqrtf(ms);
    const float f0 = x0 * r * w_lnf[0];
    const float f1 = x1 * r * w_lnf[1];

    // ---- logits -> smem staging ----
    float* lg = &logits_sh[(local * T + t) * VOCAB];
#pragma unroll
    for (int vv = 0; vv < VOCAB; ++vv) {
        const float2 tb = table_sh[vv];
        lg[vv] = f0 * tb.x + f1 * tb.y;
    }
    __syncthreads();

    // ---- coalesced store: block owns a contiguous 2560-float span ----
    float2* dst2 = (float2*)(out + (size_t)blockIdx.x * (BPB * T * VOCAB));
    const float2* src2 = (const float2*)logits_sh;
#pragma unroll
    for (int i = tid; i < BPB * T * VOCAB / 2; i += NTHREADS)
        dst2[i] = src2[i];
}

extern "C" void kernel_launch(void* const* d_in, const int* in_sizes, int n_in,
                              void* d_out, int out_size)
{
    const int*   idx     = (const int*)  d_in[0];
    const float* arc_A   = (const float*)d_in[1];
    const float* arc_st  = (const float*)d_in[2];
    const float* arc_sd  = (const float*)d_in[3];
    const float* w_ln1   = (const float*)d_in[4];
    const float* w_ln2   = (const float*)d_in[5];
    const float* w_lnf   = (const float*)d_in[6];
    const float* w_qn    = (const float*)d_in[7];
    const float* Wq      = (const float*)d_in[8];
    const float* Wk      = (const float*)d_in[9];
    const float* Wg      = (const float*)d_in[10];
    const float* Wu      = (const float*)d_in[11];
    const float* Wd      = (const float*)d_in[12];
    float* out = (float*)d_out;

    const int B = in_sizes[0] / T;           // 16384
    const int grid = B / BPB;                // 4096 blocks
    adder_model_kernel<<<grid, NTHREADS>>>(idx, arc_A, arc_st, arc_sd,
                                           w_ln1, w_ln2, w_lnf, w_qn,
                                           Wq, Wk, Wg, Wu, Wd, out);
}